// round 16
// baseline (speedup 1.0000x reference)
#include <cuda_runtime.h>
#include <cuda_fp16.h>
#include <cstdint>
#include <cstddef>
#include <math.h>

// ---------------- problem dims ----------------
#define BB 4096
#define HH 2048
#define K1 6144          // K for GEMM1: [x|h|c]
#define N1 8192          // N for GEMM1: 4 gates * 2048

// ---------------- GEMM tile config ----------------
#define BM 128
#define BN 128
#define BK 64            // fp16 elements per chunk (128B data per row)
#define ROWB 144         // smem row stride bytes (128 data + 16 pad)
#define A_TILE_BYTES (BM * ROWB)             // 18432
#define B_TILE_BYTES (BN * ROWB)             // 18432
#define ST_A 0
#define ST_B A_TILE_BYTES
#define STAGE_BYTES (A_TILE_BYTES + B_TILE_BYTES)           // 36864
#define NSTAGE 3
#define SMEM_DYN (NSTAGE * STAGE_BYTES + 128)               // 110720

// ---------------- device scratch (static; alloc APIs are forbidden) ------
__device__ __half g_A1[(size_t)BB * K1];
__device__ __half g_W1[(size_t)N1 * K1];
__device__ __half g_W2[(size_t)HH * HH];
__device__ __half g_A2[(size_t)BB * HH];
__device__ float  g_C[(size_t)BB * N1];

// ---------------- helpers ----------------
__device__ __forceinline__ uint32_t smem_u32(const void* p) {
    uint32_t a;
    asm("{ .reg .u64 t; cvta.to.shared.u64 t, %1; cvt.u32.u64 %0, t; }" : "=r"(a) : "l"(p));
    return a;
}

__device__ __forceinline__ void cp_async16(uint32_t dst, const void* src) {
    asm volatile("cp.async.cg.shared.global [%0], [%1], 16;" :: "r"(dst), "l"(src));
}

__device__ __forceinline__ void ldmatrix_x4(uint32_t* r, uint32_t addr) {
    asm volatile("ldmatrix.sync.aligned.m8n8.x4.shared.b16 {%0,%1,%2,%3}, [%4];"
        : "=r"(r[0]), "=r"(r[1]), "=r"(r[2]), "=r"(r[3]) : "r"(addr));
}

__device__ __forceinline__ void ldmatrix_x2(uint32_t* r, uint32_t addr) {
    asm volatile("ldmatrix.sync.aligned.m8n8.x2.shared.b16 {%0,%1}, [%2];"
        : "=r"(r[0]), "=r"(r[1]) : "r"(addr));
}

__device__ __forceinline__ void mma_16816(float* c, const uint32_t* a, const uint32_t* b) {
    asm volatile(
        "mma.sync.aligned.m16n8k16.row.col.f32.f16.f16.f32 "
        "{%0,%1,%2,%3}, {%4,%5,%6,%7}, {%8,%9}, {%0,%1,%2,%3};"
        : "+f"(c[0]), "+f"(c[1]), "+f"(c[2]), "+f"(c[3])
        : "r"(a[0]), "r"(a[1]), "r"(a[2]), "r"(a[3]), "r"(b[0]), "r"(b[1]));
}

// fast activations (__expf: ~1e-6 rel err, negligible vs fp16 GEMM error)
__device__ __forceinline__ float sigmoid_f(float x) { return 1.0f / (1.0f + __expf(-x)); }
__device__ __forceinline__ float tanh_f(float x)    { return 2.0f / (1.0f + __expf(-2.0f * x)) - 1.0f; }

// convert 8 floats (2x float4) -> uint4 of 8 halves
__device__ __forceinline__ uint4 pack8(const float4 a, const float4 b) {
    uint4 r;
    __half2 h0 = __floats2half2_rn(a.x, a.y);
    __half2 h1 = __floats2half2_rn(a.z, a.w);
    __half2 h2 = __floats2half2_rn(b.x, b.y);
    __half2 h3 = __floats2half2_rn(b.z, b.w);
    r.x = *reinterpret_cast<uint32_t*>(&h0);
    r.y = *reinterpret_cast<uint32_t*>(&h1);
    r.z = *reinterpret_cast<uint32_t*>(&h2);
    r.w = *reinterpret_cast<uint32_t*>(&h3);
    return r;
}

// ---------------- packing kernels (8 elements / thread) ----------------
__global__ void pack_A1(const float* __restrict__ x, const float* __restrict__ h,
                        const float* __restrict__ c) {
    const int tid = blockIdx.x * 256 + threadIdx.x;        // 0 .. BB*K1/8-1
    const int m = tid / (K1 / 8);
    const int k = (tid - m * (K1 / 8)) * 8;
    const float* src;
    if (k < HH)          src = x + (size_t)m * HH + k;
    else if (k < 2 * HH) src = h + (size_t)m * HH + (k - HH);
    else                 src = c + (size_t)m * HH + (k - 2 * HH);
    float4 a = *reinterpret_cast<const float4*>(src);
    float4 b = *reinterpret_cast<const float4*>(src + 4);
    *reinterpret_cast<uint4*>(g_A1 + (size_t)m * K1 + k) = pack8(a, b);
}

__global__ void pack_W1(const float* __restrict__ Wix, const float* __restrict__ Wfx,
                        const float* __restrict__ Wcx, const float* __restrict__ Wox,
                        const float* __restrict__ Wih, const float* __restrict__ Wic,
                        const float* __restrict__ Wfh, const float* __restrict__ Wfc,
                        const float* __restrict__ Wch, const float* __restrict__ Woh) {
    const int tid = blockIdx.x * 256 + threadIdx.x;        // 0 .. N1*K1/8-1
    const int row = tid / (K1 / 8);
    const int k = (tid - row * (K1 / 8)) * 8;
    const int gate = row >> 11;
    const int j = row & 2047;
    const int seg = k >> 11;
    const int kk = k & 2047;
    const float* W = nullptr;
    switch (gate * 3 + seg) {
        case 0:  W = Wix; break;
        case 1:  W = Wih; break;
        case 2:  W = Wic; break;
        case 3:  W = Wfx; break;
        case 4:  W = Wfh; break;
        case 5:  W = Wfc; break;
        case 6:  W = Wcx; break;
        case 7:  W = Wch; break;
        case 9:  W = Wox; break;
        case 10: W = Woh; break;
        default: break;   // gate g/o c-slot: zero (never read: variable-K skips it)
    }
    uint4 out;
    if (W) {
        const float* src = W + (size_t)j * HH + kk;
        float4 a = *reinterpret_cast<const float4*>(src);
        float4 b = *reinterpret_cast<const float4*>(src + 4);
        out = pack8(a, b);
    } else {
        out = make_uint4(0, 0, 0, 0);
    }
    *reinterpret_cast<uint4*>(g_W1 + (size_t)row * K1 + k) = out;
}

__global__ void pack_W2(const float* __restrict__ Woc) {
    const int tid = blockIdx.x * 256 + threadIdx.x;        // 0 .. HH*HH/8-1
    const size_t i = (size_t)tid * 8;
    float4 a = *reinterpret_cast<const float4*>(Woc + i);
    float4 b = *reinterpret_cast<const float4*>(Woc + i + 4);
    *reinterpret_cast<uint4*>(g_W2 + i) = pack8(a, b);
}

// ---------------- GEMM: C = A*B^T (fp16 operands, fp32 accumulate) ----------
// cp.async 3-stage pipeline, BK=64, wait_group 1, one barrier per chunk.
// CTA tile 128x128, 8 warps as 2(M) x 4(N), warp tile 64x32, 2 CTAs/SM.
// which==0: GEMM1, fp32 store to g_C.
// which==1: GEMM2 (c_next @ Woc^T) with FUSED o-gate epilogue:
//           o = sigmoid(acc + g_C[.,6144+j] + biases) * tanh(c_next); h = o*tanh(c_next)
__global__ void __launch_bounds__(256, 2)
gemm_kernel(int which,
            const float* __restrict__ b_ox, const float* __restrict__ b_oh,
            const float* __restrict__ b_oc, float* __restrict__ out) {
    const __half *Ap, *Bp;
    int K, Keff;
    const size_t brow0 = (size_t)blockIdx.y * BN;
    if (which == 0) {
        Ap = g_A1; Bp = g_W1;
        K = K1;
        Keff = (brow0 >= 4096) ? 4096 : 6144;   // gates g,o have zero c-slot
    } else {
        Ap = g_A2; Bp = g_W2;
        K = HH; Keff = HH;
    }
    const size_t arow0 = (size_t)blockIdx.x * BM;
    const int nchunk = Keff / BK;
    const int tid = threadIdx.x;
    const int lane = tid & 31;
    const int wid = tid >> 5;
    const int warpM = wid & 1;   // 2 warps over M: 64 rows each
    const int warpN = wid >> 1;  // 4 warps over N: 32 cols each

    extern __shared__ char dsmem[];
    const uint32_t sb = (smem_u32(dsmem) + 127u) & ~127u;

    // loader for chunk j into stage s (always commits, possibly empty group)
    auto load_chunk = [&](int j, int s) {
        if (j < nchunk) {
            const uint32_t stage = sb + s * STAGE_BYTES;
            const size_t kof = (size_t)j * BK;
            #pragma unroll
            for (int it = 0; it < 8; ++it) {
                int idx = tid + it * 256;        // 0..2047
                int g = idx & 7;                 // 16B segment within 128B row
                int rs = idx >> 3;               // 0..255: tile-row id
                const __half* src;
                uint32_t dstbase;
                int r;
                if (rs < 128) { r = rs;       src = Ap + (arow0 + r) * K + kof; dstbase = stage + ST_A; }
                else          { r = rs - 128; src = Bp + (brow0 + r) * K + kof; dstbase = stage + ST_B; }
                uint32_t dst = dstbase + (uint32_t)r * ROWB + (uint32_t)g * 16u;
                cp_async16(dst, (const void*)(src + g * 8));
            }
        }
        asm volatile("cp.async.commit_group;" ::: "memory");
    };

    float acc[4][4][4];
    #pragma unroll
    for (int mi = 0; mi < 4; ++mi)
        #pragma unroll
        for (int ni = 0; ni < 4; ++ni)
            #pragma unroll
            for (int q = 0; q < 4; ++q) acc[mi][ni][q] = 0.0f;

    load_chunk(0, 0);
    load_chunk(1, 1);

    // fragment double buffers
    uint32_t aR[2][4][4];
    uint32_t bR[2][4][2];

    for (int j = 0; j < nchunk; ++j) {
        const int s = j % NSTAGE;
        // chunk j ready (j+1 may be in flight); recycle slot (j+2)%3.
        asm volatile("cp.async.wait_group 1;" ::: "memory");
        __syncthreads();          // all warps done with compute(j-1) -> slot (j+2)%3 free
        load_chunk(j + 2, (j + 2) % NSTAGE);

        const uint32_t stage = sb + s * STAGE_BYTES;
        // A: ldmatrix.x4 address — lanes 0..15 rows, 16..31 rows at +16B
        const uint32_t a_0 = stage + ST_A + (warpM * 64 + (lane & 15)) * ROWB + (lane >> 4) * 16;
        // B: ldmatrix.x2 address — lanes 0..7 rows at koff, lanes 8..15 at +16B
        const uint32_t b_0 = stage + ST_B + (warpN * 32 + (lane & 7)) * ROWB + ((lane >> 3) & 1) * 16;

        // prologue: fragments for ks=0
        #pragma unroll
        for (int mi = 0; mi < 4; ++mi)
            ldmatrix_x4(aR[0][mi], a_0 + mi * 16 * ROWB);
        #pragma unroll
        for (int ni = 0; ni < 4; ++ni)
            ldmatrix_x2(bR[0][ni], b_0 + ni * 8 * ROWB);

        #pragma unroll
        for (int ks = 0; ks < 4; ++ks) {
            const int cur = ks & 1;
            if (ks < 3) {
                const uint32_t koff = (ks + 1) * 32;
                #pragma unroll
                for (int mi = 0; mi < 4; ++mi)
                    ldmatrix_x4(aR[cur ^ 1][mi], a_0 + mi * 16 * ROWB + koff);
                #pragma unroll
                for (int ni = 0; ni < 4; ++ni)
                    ldmatrix_x2(bR[cur ^ 1][ni], b_0 + ni * 8 * ROWB + koff);
            }
            #pragma unroll
            for (int ni = 0; ni < 4; ++ni)
                #pragma unroll
                for (int mi = 0; mi < 4; ++mi)
                    mma_16816(acc[mi][ni], aR[cur][mi], bR[cur][ni]);
        }
    }

    if (which == 0) {
        // GEMM1 epilogue: fp32 store to g_C
        #pragma unroll
        for (int mi = 0; mi < 4; ++mi) {
            const size_t m0 = arow0 + warpM * 64 + mi * 16 + (lane >> 2);
            #pragma unroll
            for (int ni = 0; ni < 4; ++ni) {
                const size_t n0 = brow0 + warpN * 32 + ni * 8 + (lane & 3) * 2;
                float2 v0 = make_float2(acc[mi][ni][0], acc[mi][ni][1]);
                float2 v1 = make_float2(acc[mi][ni][2], acc[mi][ni][3]);
                *reinterpret_cast<float2*>(g_C + m0 * N1 + n0)       = v0;
                *reinterpret_cast<float2*>(g_C + (m0 + 8) * N1 + n0) = v1;
            }
        }
    } else {
        // GEMM2 fused o-gate epilogue
        const size_t n = (size_t)BB * HH;
        #pragma unroll
        for (int mi = 0; mi < 4; ++mi) {
            const size_t m0 = arow0 + warpM * 64 + mi * 16 + (lane >> 2);
            #pragma unroll
            for (int ni = 0; ni < 4; ++ni) {
                const size_t j0 = brow0 + warpN * 32 + ni * 8 + (lane & 3) * 2;
                float2 bx = *reinterpret_cast<const float2*>(b_ox + j0);
                float2 bh = *reinterpret_cast<const float2*>(b_oh + j0);
                float2 bc = *reinterpret_cast<const float2*>(b_oc + j0);
                #pragma unroll
                for (int rr = 0; rr < 2; ++rr) {
                    const size_t m = m0 + rr * 8;
                    const size_t base = m * HH + j0;
                    float2 op1 = *reinterpret_cast<const float2*>(g_C + m * N1 + 6144 + j0);
                    float2 cn  = *reinterpret_cast<const float2*>(out + 2 * n + base);
                    float a0 = acc[mi][ni][rr * 2 + 0];
                    float a1 = acc[mi][ni][rr * 2 + 1];
                    float t0 = tanh_f(cn.x), t1 = tanh_f(cn.y);
                    float o0 = sigmoid_f(a0 + op1.x + bx.x + bh.x + bc.x) * t0;
                    float o1 = sigmoid_f(a1 + op1.y + bx.y + bh.y + bc.y) * t1;
                    *reinterpret_cast<float2*>(out + base)     = make_float2(o0, o1);
                    *reinterpret_cast<float2*>(out + n + base) = make_float2(o0 * t0, o1 * t1);
                }
            }
        }
    }
}

// ---------------- elementwise 1 (4 elems/thread): gates -> c_next; pack A2 --
__global__ void ew1(const float* __restrict__ c,
                    const float* __restrict__ b_ix, const float* __restrict__ b_ih,
                    const float* __restrict__ b_ic,
                    const float* __restrict__ b_fx, const float* __restrict__ b_fh,
                    const float* __restrict__ b_fc,
                    const float* __restrict__ b_cx, const float* __restrict__ b_ch,
                    float* __restrict__ out) {
    const size_t n = (size_t)BB * HH;
    const int tid = blockIdx.x * 256 + threadIdx.x;        // 0 .. BB*HH/4-1
    const int m = tid / (HH / 4);
    const int j = (tid - m * (HH / 4)) * 4;
    const float* crow = g_C + (size_t)m * N1;

    float4 iv = *reinterpret_cast<const float4*>(crow + j);
    float4 fv = *reinterpret_cast<const float4*>(crow + 2048 + j);
    float4 gv = *reinterpret_cast<const float4*>(crow + 4096 + j);
    float4 cv = *reinterpret_cast<const float4*>(c + (size_t)m * HH + j);
    float4 bix = *reinterpret_cast<const float4*>(b_ix + j);
    float4 bih = *reinterpret_cast<const float4*>(b_ih + j);
    float4 bic = *reinterpret_cast<const float4*>(b_ic + j);
    float4 bfx = *reinterpret_cast<const float4*>(b_fx + j);
    float4 bfh = *reinterpret_cast<const float4*>(b_fh + j);
    float4 bfc = *reinterpret_cast<const float4*>(b_fc + j);
    float4 bcx = *reinterpret_cast<const float4*>(b_cx + j);
    float4 bch = *reinterpret_cast<const float4*>(b_ch + j);

    float cn[4];
    {
        float ii, ff, gg;
        ii = sigmoid_f(iv.x + bix.x + bih.x + bic.x);
        ff = sigmoid_f(fv.x + bfx.x + bfh.x + bfc.x);
        gg = tanh_f(gv.x + bcx.x + bch.x);
        cn[0] = ff * cv.x + ii * gg;
        ii = sigmoid_f(iv.y + bix.y + bih.y + bic.y);
        ff = sigmoid_f(fv.y + bfx.y + bfh.y + bfc.y);
        gg = tanh_f(gv.y + bcx.y + bch.y);
        cn[1] = ff * cv.y + ii * gg;
        ii = sigmoid_f(iv.z + bix.z + bih.z + bic.z);
        ff = sigmoid_f(fv.z + bfx.z + bfh.z + bfc.z);
        gg = tanh_f(gv.z + bcx.z + bch.z);
        cn[2] = ff * cv.z + ii * gg;
        ii = sigmoid_f(iv.w + bix.w + bih.w + bic.w);
        ff = sigmoid_f(fv.w + bfx.w + bfh.w + bfc.w);
        gg = tanh_f(gv.w + bcx.w + bch.w);
        cn[3] = ff * cv.w + ii * gg;
    }
    const size_t base = (size_t)m * HH + j;
    *reinterpret_cast<float4*>(out + 2 * n + base) = make_float4(cn[0], cn[1], cn[2], cn[3]);
    __half2 h0 = __floats2half2_rn(cn[0], cn[1]);
    __half2 h1 = __floats2half2_rn(cn[2], cn[3]);
    uint2 hp;
    hp.x = *reinterpret_cast<uint32_t*>(&h0);
    hp.y = *reinterpret_cast<uint32_t*>(&h1);
    *reinterpret_cast<uint2*>(g_A2 + base) = hp;
}

// ---------------- launch ----------------
extern "C" void kernel_launch(void* const* d_in, const int* in_sizes, int n_in,
                              void* d_out, int out_size) {
    const float* x    = (const float*)d_in[0];
    const float* h    = (const float*)d_in[1];
    const float* c    = (const float*)d_in[2];
    const float* W_ix = (const float*)d_in[3];
    const float* b_ix = (const float*)d_in[4];
    const float* W_fx = (const float*)d_in[5];
    const float* b_fx = (const float*)d_in[6];
    const float* W_cx = (const float*)d_in[7];
    const float* b_cx = (const float*)d_in[8];
    const float* W_ox = (const float*)d_in[9];
    const float* b_ox = (const float*)d_in[10];
    const float* W_ih = (const float*)d_in[11];
    const float* b_ih = (const float*)d_in[12];
    const float* W_ic = (const float*)d_in[13];
    const float* b_ic = (const float*)d_in[14];
    const float* W_fh = (const float*)d_in[15];
    const float* b_fh = (const float*)d_in[16];
    const float* W_fc = (const float*)d_in[17];
    const float* b_fc = (const float*)d_in[18];
    const float* W_ch = (const float*)d_in[19];
    const float* b_ch = (const float*)d_in[20];
    const float* W_oh = (const float*)d_in[21];
    const float* b_oh = (const float*)d_in[22];
    const float* W_oc = (const float*)d_in[23];
    const float* b_oc = (const float*)d_in[24];
    float* out = (float*)d_out;

    cudaFuncSetAttribute(gemm_kernel, cudaFuncAttributeMaxDynamicSharedMemorySize, SMEM_DYN);

    pack_A1<<<(BB * K1 / 8) / 256, 256>>>(x, h, c);                       // 12288 blocks
    pack_W1<<<((size_t)N1 * K1 / 8) / 256, 256>>>(W_ix, W_fx, W_cx, W_ox, W_ih, W_ic,
                                                  W_fh, W_fc, W_ch, W_oh); // 24576 blocks
    pack_W2<<<(HH * HH / 8) / 256, 256>>>(W_oc);                          // 2048 blocks

    dim3 g1(BB / BM, N1 / BN);   // 32 x 64
    gemm_kernel<<<g1, 256, SMEM_DYN>>>(0, nullptr, nullptr, nullptr, out);

    ew1<<<(BB * HH / 4) / 256, 256>>>(c, b_ix, b_ih, b_ic, b_fx, b_fh, b_fc, b_cx, b_ch, out);

    dim3 g2(BB / BM, HH / BN);   // 32 x 16
    gemm_kernel<<<g2, 256, SMEM_DYN>>>(1, b_ox, b_oh, b_oc, out);
}